// round 6
// baseline (speedup 1.0000x reference)
#include <cuda_runtime.h>
#include <cuda_fp16.h>
#include <cstdint>
#include <cfloat>

// Quantize_8881992368326 — VQ-VAE eval forward.
// m16n8k16 f16 MMA, 32 rows/warp (B-fragment reuse x2), biased 1-LOP3 sort keys,
// exact fp32 fallback, fused deterministic finalize.
// x: [131072, 64] f32, embed: [64, 512] f32 (dim-major).
// out (f32): quantize[131072*64] | diff[1] | embed_ind[131072]

#define DIM     64
#define NE      512
#define NROWS   (32*64*64)
#define TILE_M  512
#define NTILES  (NROWS / TILE_M)   /* 256 */
#define GRIDSZ  148
#define TPB     512
#define NWARP   (TPB/32)
#define MARGIN  0.75f
#define BIAS    2048.0f

// SMEM layout (bytes)
#define OFF_B      0                          /* f16 B: 512 codes x 128B, swizzled */
#define OFF_NORMB  65536                      /* 512 f32: 2048 - ||e||^2 */
#define OFF_NORM   67584                      /* 512 f32: exact ||e||^2 */
#define OFF_CB     69632                      /* fp32 codebook 512 x 256B, XOR swizzled */
#define OFF_SCMAX  (OFF_CB + NE*256)          /* 512 rows x 8 chunk-max f32 */
#define OFF_WIDX   (OFF_SCMAX + TILE_M*8*4)   /* 512 int */
#define OFF_RED    (OFF_WIDX + TILE_M*4)      /* 16 f32 */
#define SMEM_TOTAL (OFF_RED + NWARP*4)        /* ~214 KB */

__device__ float g_partials[GRIDSZ];
__device__ unsigned int g_done;

__device__ __forceinline__ uint32_t f2h2(float lo, float hi) {
    uint32_t r;
    asm("cvt.rn.f16x2.f32 %0, %1, %2;" : "=r"(r) : "f"(hi), "f"(lo));
    return r;
}
__device__ __forceinline__ void mma_f16(float& c0, float& c1, float& c2, float& c3,
                                        uint32_t a0, uint32_t a1, uint32_t a2, uint32_t a3,
                                        uint32_t b0, uint32_t b1) {
    asm volatile("mma.sync.aligned.m16n8k16.row.col.f32.f16.f16.f32 "
                 "{%0,%1,%2,%3}, {%4,%5,%6,%7}, {%8,%9}, {%0,%1,%2,%3};"
                 : "+f"(c0), "+f"(c1), "+f"(c2), "+f"(c3)
                 : "r"(a0), "r"(a1), "r"(a2), "r"(a3), "r"(b0), "r"(b1));
}
// biased-positive score -> sortable key (1 LOP3), idxc = 511 - j in low 9 bits
__device__ __forceinline__ uint32_t skey(float s, uint32_t idxc) {
    return (__float_as_uint(s) & 0xfffffe00u) | idxc;
}
__device__ __forceinline__ float keyf_s(uint32_t k) {      // back to unbiased s-space
    return __uint_as_float(k & 0xfffffe00u) - BIAS;
}
__device__ __forceinline__ void upd(uint32_t& m1, uint32_t& m2, uint32_t& cm, uint32_t k) {
    cm = max(cm, k);
    m2 = max(m2, min(m1, k));
    m1 = max(m1, k);
}
// fp32 codebook swizzled addressing: float k of code j
__device__ __forceinline__ uint32_t cb_off(int j, int kb /*byte offset in row*/) {
    return OFF_CB + (uint32_t)(j * 256) + (((uint32_t)kb) ^ (((uint32_t)(j & 15)) << 4));
}

__global__ __launch_bounds__(TPB, 1)
void vq_kernel(const float* __restrict__ x,
               const float* __restrict__ embed,
               float* __restrict__ out_q,
               float* __restrict__ out_idx,
               float* __restrict__ out_diff)
{
    extern __shared__ char smem[];
    float* snormb = (float*)(smem + OFF_NORMB);
    float* snorm  = (float*)(smem + OFF_NORM);
    float* scmaxf = (float*)(smem + OFF_SCMAX);
    int*   swidx  = (int*)(smem + OFF_WIDX);
    float* sred   = (float*)(smem + OFF_RED);

    const int tid  = threadIdx.x;
    const int lane = tid & 31;
    const int wid  = tid >> 5;
    const int gid  = lane >> 2;
    const int tig  = lane & 3;

    // ---- build smem ----
    for (int i = tid; i < DIM * NE; i += TPB) {            // coalesced read of embed
        int k = i >> 9, j = i & 511;
        *(float*)(smem + cb_off(j, k * 4)) = embed[i];
    }
    __syncthreads();
    for (int j = tid; j < NE; j += TPB) {
        float n = 0.f;
        #pragma unroll
        for (int k = 0; k < DIM; k++) {
            float v = *(const float*)(smem + cb_off(j, k * 4));
            n = fmaf(v, v, n);
        }
        snorm[j]  = n;
        snormb[j] = BIAS - n;
    }
    for (int i = tid; i < NE * 16; i += TPB) {             // f16 B fill (float2 source reads)
        int j = i >> 4, p = i & 15;
        int blk = p >> 2, s2 = p & 3;                      // two s per iter
        #pragma unroll
        for (int hh = 0; hh < 2; hh++) {
            int s = s2 * 2 + hh;
            int P = (s >> 1) + ((s & 1) << 2);
            int k = blk * 16 + P * 2;
            float2 e2 = *(const float2*)(smem + cb_off(j, k * 4));
            uint32_t off = (uint32_t)(j * 128) +
                           (((uint32_t)(blk * 32 + s * 4)) ^ (((uint32_t)(j & 3)) << 5));
            *(uint32_t*)(smem + OFF_B + off) = f2h2(e2.x, e2.y);
        }
    }
    __syncthreads();

    const uint32_t bsw = ((uint32_t)(gid & 3)) << 5;
    float blockdiff = 0.f;

    for (int t = blockIdx.x; t < NTILES; t += GRIDSZ) {
        const int rowbase = t * TILE_M + wid * 32;

        // ---- A fragments: 2 m16-sets (rows +0..15, +16..31), 4 k-steps
        uint32_t a[2][4][4];
        #pragma unroll
        for (int ms = 0; ms < 2; ms++) {
            const float* xr0 = x + (size_t)(rowbase + ms * 16 + gid) * DIM;
            const float* xr8 = xr0 + 8 * DIM;
            #pragma unroll
            for (int ks = 0; ks < 4; ks++) {
                float2 p;
                p = *(const float2*)(xr0 + ks * 16 + 2 * tig);     a[ms][ks][0] = f2h2(p.x, p.y);
                p = *(const float2*)(xr8 + ks * 16 + 2 * tig);     a[ms][ks][1] = f2h2(p.x, p.y);
                p = *(const float2*)(xr0 + ks * 16 + 2 * tig + 8); a[ms][ks][2] = f2h2(p.x, p.y);
                p = *(const float2*)(xr8 + ks * 16 + 2 * tig + 8); a[ms][ks][3] = f2h2(p.x, p.y);
            }
        }

        // state index st = ms*2 + h  (h=0: row gid, h=1: row gid+8)
        uint32_t m1[4] = {0u,0u,0u,0u}, m2[4] = {0u,0u,0u,0u};

        #pragma unroll 1
        for (int chunk = 0; chunk < 8; chunk++) {
            uint32_t cm[4] = {0u,0u,0u,0u};
            #pragma unroll
            for (int sub = 0; sub < 2; sub++) {
                const int j0 = chunk * 64 + sub * 32;
                float acc[2][4][4];
                #pragma unroll
                for (int ms = 0; ms < 2; ms++)
                    #pragma unroll
                    for (int nt = 0; nt < 4; nt++)
                        #pragma unroll
                        for (int q = 0; q < 4; q++) acc[ms][nt][q] = 0.f;

                #pragma unroll
                for (int ks = 0; ks < 4; ks++) {
                    #pragma unroll
                    for (int nt = 0; nt < 4; nt++) {
                        uint32_t off = (uint32_t)((j0 + nt * 8 + gid) * 128) +
                                       (((uint32_t)(ks * 32 + tig * 8)) ^ bsw);
                        uint2 b = *(const uint2*)(smem + OFF_B + off);
                        mma_f16(acc[0][nt][0], acc[0][nt][1], acc[0][nt][2], acc[0][nt][3],
                                a[0][ks][0], a[0][ks][1], a[0][ks][2], a[0][ks][3], b.x, b.y);
                        mma_f16(acc[1][nt][0], acc[1][nt][1], acc[1][nt][2], acc[1][nt][3],
                                a[1][ks][0], a[1][ks][1], a[1][ks][2], a[1][ks][3], b.x, b.y);
                    }
                }

                // ---- epilogue: biased scores, 1-LOP3 keys, top2 + chunk max
                #pragma unroll
                for (int nt = 0; nt < 4; nt++) {
                    const int jb = j0 + nt * 8 + 2 * tig;
                    float2 nb = *(const float2*)(snormb + jb);
                    uint32_t ic0 = (uint32_t)(511 - jb);
                    uint32_t ic1 = ic0 - 1;
                    #pragma unroll
                    for (int ms = 0; ms < 2; ms++) {
                        #pragma unroll
                        for (int h = 0; h < 2; h++) {
                            int st = ms * 2 + h;
                            float s0 = fmaf(2.f, acc[ms][nt][h * 2 + 0], nb.x);
                            float s1 = fmaf(2.f, acc[ms][nt][h * 2 + 1], nb.y);
                            upd(m1[st], m2[st], cm[st], skey(s0, ic0));
                            upd(m1[st], m2[st], cm[st], skey(s1, ic1));
                        }
                    }
                }
            }
            // chunk max -> smem (64-code granularity)
            #pragma unroll
            for (int st = 0; st < 4; st++) {
                uint32_t v = cm[st];
                v = max(v, __shfl_xor_sync(0xffffffffu, v, 1));
                v = max(v, __shfl_xor_sync(0xffffffffu, v, 2));
                if (tig == 0) {
                    int lrow = wid * 32 + (st >> 1) * 16 + (st & 1) * 8 + gid;
                    scmaxf[lrow * 8 + chunk] = keyf_s(v);
                }
            }
        }

        // ---- quad merge
        #pragma unroll
        for (int st = 0; st < 4; st++) {
            #pragma unroll
            for (int off = 1; off <= 2; off <<= 1) {
                uint32_t om1 = __shfl_xor_sync(0xffffffffu, m1[st], off);
                uint32_t om2 = __shfl_xor_sync(0xffffffffu, m2[st], off);
                uint32_t lo = min(m1[st], om1);
                m1[st] = max(m1[st], om1);
                m2[st] = max(max(m2[st], om2), lo);
            }
        }

        int jwin[4]; float bestf[4], gapf[4];
        #pragma unroll
        for (int st = 0; st < 4; st++) {
            jwin[st]  = 511 - (int)(m1[st] & 511u);
            bestf[st] = keyf_s(m1[st]);
            gapf[st]  = bestf[st] - keyf_s(m2[st]);
        }

        __syncwarp();

        // ---- exact fp32 fallback (rare)
        #pragma unroll 1
        for (int st = 0; st < 4; st++) {
            unsigned mask = __ballot_sync(0xffffffffu, (tig == 0) && (gapf[st] < MARGIN));
            while (mask) {
                int l = __ffs(mask) - 1; mask &= mask - 1;
                int g = l >> 2;
                int lrow = wid * 32 + (st >> 1) * 16 + (st & 1) * 8 + g;
                float thr = __shfl_sync(0xffffffffu, bestf[st], l) - MARGIN;
                const float4* xr4 = (const float4*)(x + (size_t)(t * TILE_M + lrow) * DIM);

                float bw = -FLT_MAX; int wj = NE;
                for (int ch = 0; ch < 8; ch++) {
                    if (scmaxf[lrow * 8 + ch] < thr) continue;
                    #pragma unroll
                    for (int half = 0; half < 2; half++) {
                        int j = ch * 64 + half * 32 + lane;
                        float d0 = 0.f, d1 = 0.f, d2 = 0.f, d3 = 0.f;
                        #pragma unroll
                        for (int v = 0; v < 16; v++) {
                            float4 ev = *(const float4*)(smem + cb_off(j, v * 16));
                            float4 fv = xr4[v];
                            d0 = fmaf(fv.x, ev.x, d0); d1 = fmaf(fv.y, ev.y, d1);
                            d2 = fmaf(fv.z, ev.z, d2); d3 = fmaf(fv.w, ev.w, d3);
                        }
                        float s = fmaf(2.f, (d0 + d1) + (d2 + d3), -snorm[j]);
                        if (s > bw || (s == bw && j < wj)) { bw = s; wj = j; }
                    }
                }
                #pragma unroll
                for (int off = 16; off > 0; off >>= 1) {
                    float ob = __shfl_xor_sync(0xffffffffu, bw, off);
                    int   oj = __shfl_xor_sync(0xffffffffu, wj, off);
                    if (ob > bw || (ob == bw && oj < wj)) { bw = ob; wj = oj; }
                }
                if (lane == l) jwin[st] = wj;
            }
        }

        if (tig == 0) {
            #pragma unroll
            for (int st = 0; st < 4; st++)
                swidx[wid * 32 + (st >> 1) * 16 + (st & 1) * 8 + gid] = jwin[st];
        }
        __syncthreads();

        // ---- output gather + exact diff
        const float4* xin = (const float4*)(x + (size_t)t * TILE_M * DIM);
        float4* oq = (float4*)(out_q + (size_t)t * TILE_M * DIM);
        float td = 0.f;
        #pragma unroll
        for (int it = 0; it < (TILE_M * 16) / TPB; it++) {
            int i = tid + it * TPB;
            int row = i >> 4, v = i & 15;
            float4 e = *(const float4*)(smem + cb_off(swidx[row], v * 16));
            float4 xv = xin[i];
            oq[i] = e;
            float d0 = e.x - xv.x, d1 = e.y - xv.y, d2 = e.z - xv.z, d3 = e.w - xv.w;
            td = fmaf(d0, d0, td); td = fmaf(d1, d1, td);
            td = fmaf(d2, d2, td); td = fmaf(d3, d3, td);
        }
        out_idx[(size_t)t * TILE_M + tid] = (float)swidx[tid];

        #pragma unroll
        for (int off = 16; off > 0; off >>= 1)
            td += __shfl_down_sync(0xffffffffu, td, off);
        if (lane == 0) sred[wid] = td;
        __syncthreads();
        if (tid == 0) {
            float s = 0.f;
            #pragma unroll
            for (int w = 0; w < NWARP; w++) s += sred[w];
            blockdiff += s;
        }
        __syncthreads();
    }

    // ---- fused deterministic finalize
    if (tid == 0) {
        g_partials[blockIdx.x] = blockdiff;
        __threadfence();
        unsigned int prev = atomicAdd(&g_done, 1u);
        if (prev == GRIDSZ - 1) {
            float s = 0.f;
            #pragma unroll 4
            for (int i = 0; i < GRIDSZ; i++) s += g_partials[i];
            *out_diff = s * (1.0f / (float)((size_t)NROWS * DIM));
            g_done = 0;
            __threadfence();
        }
    }
}

extern "C" void kernel_launch(void* const* d_in, const int* in_sizes, int n_in,
                              void* d_out, int out_size)
{
    const float* x     = (const float*)d_in[0];
    const float* embed = (const float*)d_in[1];

    float* out      = (float*)d_out;
    float* out_q    = out;
    float* out_diff = out + (size_t)NROWS * DIM;
    float* out_idx  = out + (size_t)NROWS * DIM + 1;

    cudaFuncSetAttribute(vq_kernel, cudaFuncAttributeMaxDynamicSharedMemorySize, SMEM_TOTAL);

    vq_kernel<<<GRIDSZ, TPB, SMEM_TOTAL>>>(x, embed, out_q, out_idx, out_diff);
}